// round 15
// baseline (speedup 1.0000x reference)
#include <cuda_runtime.h>
#include <cstdint>

#define NN 100000
#define NP 100032
#define EI 800000
#define EE 400000
#define HH 128
#define GG 256
#define N_LAYERS 4
#define NB_NODE 3125       // 3125*32 = 100000
#define NB_CNT  4688       // covers EI+EE threads
#define PREP_B 98
#define PREP_T 256
#define PREP_NT (PREP_B*PREP_T)

// transform v2: TM=32 rows, ONE matrix per CTA, 2 CTAs/SM
// 512 threads = 16 row-groups (2 rows) x 32 col-groups (4 cols)
#define TM32 32
#define NT32 3126          // NP/32
#define AST 132
#define T_B0 16384
#define T_B1 (16384 + 4224)            // 4224 = 32*AST
#define SMEM_TRANS ((16384 + 2*4224)*sizeof(float))   // 99328 B

// ---------------- scratch ----------------
__device__ float g_h [NP*HH];
__device__ float g_vp[NP*HH];
__device__ float g_vl[NP*HH];
__device__ float g_Ai[NP*HH];   // Hp = h @ W_i
__device__ float g_Ae[NP*HH];   // Hl = h @ W_e
__device__ float g_wint[EE];
__device__ int   g_degi[NN];
__device__ int   g_dege[NN];
__device__ float g_sif[NP];
__device__ float g_bfi[NP];
__device__ float g_sef[NP];
__device__ float g_bfe[NP];
__device__ int   g_offi[NN+1];
__device__ int   g_offe[NN+1];
__device__ int   g_curi[NN];
__device__ int   g_cure[NN];
__device__ int   g_srci[EI];
__device__ float g_wi[EI];
__device__ int   g_srce[EE];
__device__ float g_we[EE];
__device__ int   g_parti[128];
__device__ int   g_parte[128];
__device__ int   g_cnt1;
__device__ int   g_cnt2;
__device__ float g_pool[GG*HH];

__device__ __forceinline__ float silu_f(float x){ return x / (1.f + __expf(-x)); }
__device__ __forceinline__ unsigned long long dup2(float a){
    unsigned long long r; asm("mov.b64 %0, {%1, %1};" : "=l"(r) : "f"(a)); return r;
}
__device__ __forceinline__ void ffma2(unsigned long long& acc, unsigned long long a, unsigned long long b){
    asm("fma.rn.f32x2 %0, %1, %2, %0;" : "+l"(acc) : "l"(a), "l"(b));
}
__device__ __forceinline__ void cp16(unsigned dst, const void* src){
    asm volatile("cp.async.cg.shared.global [%0], [%1], 16;" :: "r"(dst), "l"(src));
}
__device__ __forceinline__ void cp_commit(){
    asm volatile("cp.async.commit_group;" ::: "memory");
}
__device__ __forceinline__ void cp_wait1(){
    asm volatile("cp.async.wait_group 1;" ::: "memory");
}

// ---------------- 0: pool zero + handshake reset ----------------
__global__ void k_zero(){
    int t = blockIdx.x*256 + threadIdx.x;
    if (t == 0){ g_cnt1 = 0; g_cnt2 = 0; }
    if (t < GG*HH) g_pool[t] = 0.f;
}

// ---------------- 1: node init + degree counts + inter weight ----------------
__global__ void k_init(const float* __restrict__ x, const float* __restrict__ W,
                       const float* __restrict__ b,
                       const int* __restrict__ ei, const int* __restrict__ ee,
                       const float* __restrict__ pos){
    int blk = blockIdx.x;
    if (blk < NB_NODE){
        __shared__ float Ws[35*HH];
        __shared__ float xs[32*35];
        int t = threadIdx.x;           // 256
        int n0 = blk*32;
        for (int i = t; i < 35*HH; i += 256) Ws[i] = W[i];
        for (int i = t; i < 32*35; i += 256){
            int node = i/35, k = i - node*35;
            xs[i] = x[(n0+node)*35 + k];
        }
        __syncthreads();
        int c = t & 127;
        int g = t >> 7;
        float bb = b[c];
        for (int idx = 0; idx < 16; idx++){
            int node = g*16 + idx;
            float acc = bb;
            #pragma unroll
            for (int k = 0; k < 35; k++) acc += xs[node*35+k]*Ws[k*HH+c];
            g_h[(n0+node)*HH + c] = silu_f(acc);
        }
    } else {
        int t = (blk - NB_NODE)*256 + threadIdx.x;
        if (t < EI){
            atomicAdd(&g_degi[ei[EI+t]], 1);
        } else if (t < EI+EE){
            int e = t - EI;
            int s = ee[e], d = ee[EE+e];
            float dx = pos[s*3+0]-pos[d*3+0];
            float dy = pos[s*3+1]-pos[d*3+1];
            float dz = pos[s*3+2]-pos[d*3+2];
            g_wint[e] = __expf(-(dx*dx+dy*dy+dz*dz));
            atomicAdd(&g_dege[d], 1);
        }
    }
}

// ---------------- 2: scan + offsets/cursors/factors + CSR fill ----------------
__global__ void __launch_bounds__(PREP_T) k_prep(const int* __restrict__ ei,
                                                 const float* __restrict__ ea,
                                                 const int* __restrict__ ee){
    __shared__ int s[1024];
    __shared__ int spi[128], spe[128];
    int b = blockIdx.x, b0 = b*1024, t = threadIdx.x;

    for (int pass = 0; pass < 2; pass++){
        const int* deg = pass ? g_dege : g_degi;
        int* off  = pass ? g_offe : g_offi;
        int* part = pass ? g_parte : g_parti;
        for (int i = t; i < 1024; i += 256){
            int n = b0 + i; s[i] = (n < NN) ? deg[n] : 0;
        }
        __syncthreads();
        for (int d = 1; d < 1024; d <<= 1){
            int tmp[4];
            #pragma unroll
            for (int j = 0; j < 4; j++){
                int i = t + j*256;
                tmp[j] = (i >= d) ? s[i-d] : 0;
            }
            __syncthreads();
            #pragma unroll
            for (int j = 0; j < 4; j++) s[t + j*256] += tmp[j];
            __syncthreads();
        }
        for (int i = t; i < 1024; i += 256){
            int n = b0 + i; if (n < NN) off[n+1] = s[i];
        }
        if (t == 0) atomicExch(&part[b], s[1023]);
        __syncthreads();
    }
    __threadfence();
    if (t == 0){
        atomicAdd(&g_cnt1, 1);
        int v; do { __nanosleep(128); v = atomicAdd(&g_cnt1, 0); } while (v < PREP_B);
    }
    __syncthreads();

    if (t < 128){
        spi[t] = (t < PREP_B) ? atomicAdd(&g_parti[t], 0) : 0;
        spe[t] = (t < PREP_B) ? atomicAdd(&g_parte[t], 0) : 0;
    }
    __syncthreads();
    for (int d = 1; d < 128; d <<= 1){
        int vi = 0, ve = 0;
        if (t < 128 && t >= d){ vi = spi[t-d]; ve = spe[t-d]; }
        __syncthreads();
        if (t < 128){ spi[t] += vi; spe[t] += ve; }
        __syncthreads();
    }
    int basei = (b > 0) ? spi[b-1] : 0;
    int basee = (b > 0) ? spe[b-1] : 0;

    for (int i = t; i < 1024; i += 256){
        int n = b0 + i;
        if (n >= NN) continue;
        int di = g_degi[n], de = g_dege[n];
        int oi = g_offi[n+1] + basei;
        int oe = g_offe[n+1] + basee;
        g_offi[n+1] = oi;
        g_offe[n+1] = oe;
        g_curi[n] = oi - di;
        g_cure[n] = oe - de;
        if (n == 0){ g_offi[0] = 0; g_offe[0] = 0; }
        float fdi = (float)di, fde = (float)de;
        float inv = 1.f/(fdi+1.f);
        g_sif[n] = inv;
        g_bfi[n] = fdi*inv;
        float L = logf(fde+1.f);
        g_sef[n] = L;
        g_bfe[n] = fde*L;
    }
    __threadfence();
    __syncthreads();
    if (t == 0){
        atomicAdd(&g_cnt2, 1);
        int v; do { __nanosleep(128); v = atomicAdd(&g_cnt2, 0); } while (v < PREP_B);
    }
    __syncthreads();

    for (int e = b*PREP_T + t; e < EI; e += PREP_NT){
        int s_ = ei[e], d = ei[EI+e];
        int p = atomicAdd(&g_curi[d], 1);
        g_srci[p] = s_; g_wi[p] = ea[e];
    }
    for (int e = b*PREP_T + t; e < EE; e += PREP_NT){
        int s_ = ee[e], d = ee[EE+e];
        int p = atomicAdd(&g_cure[d], 1);
        g_srce[p] = s_; g_we[p] = g_wint[e];
    }
}

// ---------------- per layer: transform v2 — one matrix per CTA, 2 CTAs/SM ----------------
// grid 296: even CTAs -> Wi/g_Ai, odd -> We/g_Ae. TM=32 rows per tile.
// 512 threads = 16 row-groups (2 rows) x 32 col-groups (4 cols)
__global__ void __launch_bounds__(512,2) k_transform(const float* __restrict__ Wi_,
                                                     const float* __restrict__ We_){
    extern __shared__ float sm[];
    float* ws = sm;                         // [128][128]
    int bid = blockIdx.x;
    int mat = bid & 1;
    const float* W = mat ? We_ : Wi_;
    float* dst = mat ? g_Ae : g_Ai;
    int tid = threadIdx.x;
    int cg = tid & 31, rg = tid >> 5;       // cg: 4 cols, rg: 2 rows
    int ccol = cg*4;
    unsigned smbase = (unsigned)__cvta_generic_to_shared(sm);

    // prologue: issue first h tile into buf0
    int tile0 = bid >> 1;
    {
        int base = tile0*TM32;
        for (int c = tid; c < 1024; c += 512){
            int row = c >> 5, seg = (c & 31)*4;
            cp16(smbase + (T_B0 + row*AST + seg)*4u, &g_h[(base+row)*HH + seg]);
        }
    }
    cp_commit();

    // load W (one matrix, 64 KB)
    for (int i = tid; i < 4096; i += 512)
        ((float4*)ws)[i] = ((const float4*)W)[i];

    int buf = 0;
    for (int tile = tile0; tile < NT32; tile += 148, buf ^= 1){
        int n0 = tile*TM32;
        int nxt = tile + 148;
        if (nxt < NT32){
            int base = nxt*TM32;
            unsigned boff = (buf ? T_B0 : T_B1);
            for (int c = tid; c < 1024; c += 512){
                int row = c >> 5, seg = (c & 31)*4;
                cp16(smbase + (boff + row*AST + seg)*4u, &g_h[(base+row)*HH + seg]);
            }
        }
        cp_commit();
        cp_wait1();
        __syncthreads();

        const float* ab = sm + (buf ? T_B1 : T_B0) + rg*2*AST;

        unsigned long long acc[2][2];
        acc[0][0]=0ull; acc[0][1]=0ull; acc[1][0]=0ull; acc[1][1]=0ull;

        #pragma unroll 2
        for (int k0 = 0; k0 < 128; k0 += 4){
            float4 a0 = *(const float4*)&ab[k0];           // row rg*2   (warp-broadcast)
            float4 a1 = *(const float4*)&ab[AST + k0];     // row rg*2+1
            #pragma unroll
            for (int kk = 0; kk < 4; kk++){
                ulonglong2 w2 = *(const ulonglong2*)&ws[(k0+kk)*128 + ccol];
                float s0 = (kk==0)?a0.x:(kk==1)?a0.y:(kk==2)?a0.z:a0.w;
                float s1 = (kk==0)?a1.x:(kk==1)?a1.y:(kk==2)?a1.z:a1.w;
                unsigned long long d0 = dup2(s0), d1 = dup2(s1);
                ffma2(acc[0][0], d0, w2.x);
                ffma2(acc[0][1], d0, w2.y);
                ffma2(acc[1][0], d1, w2.x);
                ffma2(acc[1][1], d1, w2.y);
            }
        }

        #pragma unroll
        for (int r = 0; r < 2; r++){
            int n = n0 + rg*2 + r;
            float2 p0 = *(float2*)&acc[r][0];
            float2 p1 = *(float2*)&acc[r][1];
            *(float4*)&dst[n*HH + ccol] = make_float4(p0.x, p0.y, p1.x, p1.y);
        }
        __syncthreads();   // protect buffer being refilled next iteration
    }
}

// ---------------- per layer: gather from Hp/Hl + epilogue + state + h update (+pool fuse) ----------------
__global__ void __launch_bounds__(256,5) k_gather2(const float* __restrict__ bi,
                                                   const float* __restrict__ be,
                                                   const int* __restrict__ batch,
                                                   int firstL, int lastL){
    int gw = (blockIdx.x*256 + threadIdx.x) >> 5;
    if (gw >= NN) return;
    int lane = threadIdx.x & 31;
    int c4 = lane*4;

    float sif = g_sif[gw], bfi = g_bfi[gw], sef = g_sef[gw], bfe = g_bfe[gw];
    float4 bi4 = *(const float4*)&bi[c4];
    float4 be4 = *(const float4*)&be[c4];
    float4 vo = make_float4(0,0,0,0), uo = make_float4(0,0,0,0);
    if (!firstL){
        vo = *(const float4*)&g_vp[gw*HH + c4];
        uo = *(const float4*)&g_vl[gw*HH + c4];
    }
    float4 hv = *(const float4*)&g_h[gw*HH + c4];

    float4 si;
    {
        int a0 = g_offi[gw], a1 = g_offi[gw+1];
        float4 x0 = make_float4(0,0,0,0), x1 = x0, x2 = x0, x3 = x0;
        int j = a0;
        for (; j + 4 <= a1; j += 4){
            int s0 = __ldg(&g_srci[j+0]); float w0 = __ldg(&g_wi[j+0]);
            int s1 = __ldg(&g_srci[j+1]); float w1 = __ldg(&g_wi[j+1]);
            int s2 = __ldg(&g_srci[j+2]); float w2 = __ldg(&g_wi[j+2]);
            int s3 = __ldg(&g_srci[j+3]); float w3 = __ldg(&g_wi[j+3]);
            float4 h0 = *(const float4*)&g_Ai[s0*HH + c4];
            float4 h1 = *(const float4*)&g_Ai[s1*HH + c4];
            float4 h2 = *(const float4*)&g_Ai[s2*HH + c4];
            float4 h3 = *(const float4*)&g_Ai[s3*HH + c4];
            x0.x += w0*h0.x; x0.y += w0*h0.y; x0.z += w0*h0.z; x0.w += w0*h0.w;
            x1.x += w1*h1.x; x1.y += w1*h1.y; x1.z += w1*h1.z; x1.w += w1*h1.w;
            x2.x += w2*h2.x; x2.y += w2*h2.y; x2.z += w2*h2.z; x2.w += w2*h2.w;
            x3.x += w3*h3.x; x3.y += w3*h3.y; x3.z += w3*h3.z; x3.w += w3*h3.w;
        }
        for (; j < a1; j++){
            int s = __ldg(&g_srci[j]); float w = __ldg(&g_wi[j]);
            float4 h0 = *(const float4*)&g_Ai[s*HH + c4];
            x0.x += w*h0.x; x0.y += w*h0.y; x0.z += w*h0.z; x0.w += w*h0.w;
        }
        si = make_float4(x0.x+x1.x+x2.x+x3.x, x0.y+x1.y+x2.y+x3.y,
                         x0.z+x1.z+x2.z+x3.z, x0.w+x1.w+x2.w+x3.w);
    }
    float4 se;
    {
        int a0 = g_offe[gw], a1 = g_offe[gw+1];
        float4 x0 = make_float4(0,0,0,0), x1 = x0, x2 = x0, x3 = x0;
        int j = a0;
        for (; j + 4 <= a1; j += 4){
            int s0 = __ldg(&g_srce[j+0]); float w0 = __ldg(&g_we[j+0]);
            int s1 = __ldg(&g_srce[j+1]); float w1 = __ldg(&g_we[j+1]);
            int s2 = __ldg(&g_srce[j+2]); float w2 = __ldg(&g_we[j+2]);
            int s3 = __ldg(&g_srce[j+3]); float w3 = __ldg(&g_we[j+3]);
            float4 h0 = *(const float4*)&g_Ae[s0*HH + c4];
            float4 h1 = *(const float4*)&g_Ae[s1*HH + c4];
            float4 h2 = *(const float4*)&g_Ae[s2*HH + c4];
            float4 h3 = *(const float4*)&g_Ae[s3*HH + c4];
            x0.x += w0*h0.x; x0.y += w0*h0.y; x0.z += w0*h0.z; x0.w += w0*h0.w;
            x1.x += w1*h1.x; x1.y += w1*h1.y; x1.z += w1*h1.z; x1.w += w1*h1.w;
            x2.x += w2*h2.x; x2.y += w2*h2.y; x2.z += w2*h2.z; x2.w += w2*h2.w;
            x3.x += w3*h3.x; x3.y += w3*h3.y; x3.z += w3*h3.z; x3.w += w3*h3.w;
        }
        for (; j < a1; j++){
            int s = __ldg(&g_srce[j]); float w = __ldg(&g_we[j]);
            float4 h0 = *(const float4*)&g_Ae[s*HH + c4];
            x0.x += w*h0.x; x0.y += w*h0.y; x0.z += w*h0.z; x0.w += w*h0.w;
        }
        se = make_float4(x0.x+x1.x+x2.x+x3.x, x0.y+x1.y+x2.y+x3.y,
                         x0.z+x1.z+x2.z+x3.z, x0.w+x1.w+x2.w+x3.w);
    }

    float4 v;
    v.x = silu_f(si.x*sif + bi4.x*bfi + vo.x);
    v.y = silu_f(si.y*sif + bi4.y*bfi + vo.y);
    v.z = silu_f(si.z*sif + bi4.z*bfi + vo.z);
    v.w = silu_f(si.w*sif + bi4.w*bfi + vo.w);
    float4 u;
    u.x = silu_f(se.x*sef + be4.x*bfe + uo.x);
    u.y = silu_f(se.y*sef + be4.y*bfe + uo.y);
    u.z = silu_f(se.z*sef + be4.z*bfe + uo.z);
    u.w = silu_f(se.w*sef + be4.w*bfe + uo.w);

    hv.x += v.x + u.x; hv.y += v.y + u.y; hv.z += v.z + u.z; hv.w += v.w + u.w;

    if (!lastL){
        *(float4*)&g_vp[gw*HH + c4] = v;
        *(float4*)&g_vl[gw*HH + c4] = u;
        *(float4*)&g_h[gw*HH + c4] = hv;
    } else {
        int bg = batch[gw];
        atomicAdd((float4*)&g_pool[bg*HH + c4], hv);
    }
}

// ---------------- FC head (+ degree re-zero) ----------------
__global__ void k_fc(const float* __restrict__ fcW, const float* __restrict__ fcb,
                     const float* __restrict__ gam, const float* __restrict__ bet,
                     const float* __restrict__ oW,  const float* __restrict__ ob,
                     float* __restrict__ out){
    int g = blockIdx.x, c = threadIdx.x;
    __shared__ float s[HH];
    __shared__ float red[HH];
    s[c] = g_pool[g*HH + c];
    for (int i = g*128 + c; i < NN; i += GG*128){ g_degi[i] = 0; g_dege[i] = 0; }
    __syncthreads();
    const float bns = rsqrtf(1.f + 1e-5f);
    for (int j = 0; j < 3; j++){
        const float* W = fcW + j*HH*HH;
        float acc = fcb[j*HH+c];
        #pragma unroll 8
        for (int k = 0; k < HH; k++) acc += s[k]*W[k*HH+c];
        acc = acc > 0.f ? acc : 0.01f*acc;
        acc = acc*bns*gam[j*HH+c] + bet[j*HH+c];
        __syncthreads();
        s[c] = acc;
        __syncthreads();
    }
    red[c] = s[c]*oW[c];
    __syncthreads();
    for (int o = 64; o > 0; o >>= 1){
        if (c < o) red[c] += red[c+o];
        __syncthreads();
    }
    if (c == 0) out[g] = red[0] + ob[0];
}

// ---------------- host ----------------
extern "C" void kernel_launch(void* const* d_in, const int* in_sizes, int n_in,
                              void* d_out, int out_size){
    const float* x    = (const float*)d_in[0];
    const int*   ei   = (const int*)  d_in[1];
    const int*   ee   = (const int*)  d_in[2];
    const float* pos  = (const float*)d_in[3];
    const float* ea   = (const float*)d_in[4];
    const int*   batch= (const int*)  d_in[5];
    const float* lnW  = (const float*)d_in[6];
    const float* lnb  = (const float*)d_in[7];
    const float* Wi   = (const float*)d_in[8];
    const float* bi   = (const float*)d_in[9];
    const float* We   = (const float*)d_in[10];
    const float* be   = (const float*)d_in[11];
    const float* fcW  = (const float*)d_in[12];
    const float* fcb  = (const float*)d_in[13];
    const float* gam  = (const float*)d_in[14];
    const float* bet  = (const float*)d_in[15];
    const float* oW   = (const float*)d_in[16];
    const float* ob   = (const float*)d_in[17];
    float* out = (float*)d_out;

    cudaFuncSetAttribute(k_transform, cudaFuncAttributeMaxDynamicSharedMemorySize, (int)SMEM_TRANS);

    k_zero<<<128, 256>>>();                                       // launch 1
    k_init<<<NB_NODE + NB_CNT, 256>>>(x, lnW, lnb, ei, ee, pos);  // launch 2
    k_prep<<<PREP_B, PREP_T>>>(ei, ea, ee);                       // launch 3

    for (int l = 0; l < N_LAYERS; l++){
        k_transform<<<296, 512, SMEM_TRANS>>>(Wi + l*HH*HH, We + l*HH*HH); // launch 4 (ncu capture),6,8,10
        k_gather2<<<(NN*32+255)/256, 256>>>(bi + l*HH, be + l*HH, batch,
                                            l == 0, l == N_LAYERS-1);      // launch 5,7,9,11
    }

    k_fc<<<GG, 128>>>(fcW, fcb, gam, bet, oW, ob, out);           // launch 12
}

// round 16
// speedup vs baseline: 1.3043x; 1.3043x over previous
#include <cuda_runtime.h>
#include <cstdint>

#define NN 100000
#define NP 100032
#define EI 800000
#define EE 400000
#define HH 128
#define GG 256
#define N_LAYERS 4
#define NB_NODE 3125       // 3125*32 = 100000
#define NB_CNT  4816       // covers EI+EE+GG*HH threads
#define PREP_B 98
#define PREP_T 256
#define PREP_NT (PREP_B*PREP_T)

// transform v3: pair-private 8-row strips, no block barriers in loop
#define NSTRIP 12504       // NP/8
#define NPAIRU 1184        // 148 CTAs * 8 pairs
#define W_FLOATS 32768     // 128*256
#define PB(p,b) (W_FLOATS + (p)*2112 + (b)*1056)   // floats
#define SMEM_TRANS ((W_FLOATS + 8*2112)*sizeof(float))   // 198656 B

// ---------------- scratch ----------------
__device__ float g_h [NP*HH];
__device__ float g_vp[NP*HH];
__device__ float g_vl[NP*HH];
__device__ float g_Ai[NP*HH];   // Hp = h @ W_i
__device__ float g_Ae[NP*HH];   // Hl = h @ W_e
__device__ float g_wint[EE];
__device__ int   g_degi[NN];
__device__ int   g_dege[NN];
__device__ float g_sif[NP];
__device__ float g_bfi[NP];
__device__ float g_sef[NP];
__device__ float g_bfe[NP];
__device__ int   g_offi[NN+1];
__device__ int   g_offe[NN+1];
__device__ int   g_curi[NN];
__device__ int   g_cure[NN];
__device__ int   g_srci[EI];
__device__ float g_wi[EI];
__device__ int   g_srce[EE];
__device__ float g_we[EE];
__device__ int   g_parti[128];
__device__ int   g_parte[128];
__device__ int   g_cnt1;
__device__ int   g_cnt2;
__device__ float g_pool[GG*HH];

__device__ __forceinline__ float silu_f(float x){ return x / (1.f + __expf(-x)); }
__device__ __forceinline__ unsigned long long dup2(float a){
    unsigned long long r; asm("mov.b64 %0, {%1, %1};" : "=l"(r) : "f"(a)); return r;
}
__device__ __forceinline__ void ffma2(unsigned long long& acc, unsigned long long a, unsigned long long b){
    asm("fma.rn.f32x2 %0, %1, %2, %0;" : "+l"(acc) : "l"(a), "l"(b));
}
__device__ __forceinline__ void cp16(unsigned dst, const void* src){
    asm volatile("cp.async.cg.shared.global [%0], [%1], 16;" :: "r"(dst), "l"(src));
}
__device__ __forceinline__ void cp_commit(){
    asm volatile("cp.async.commit_group;" ::: "memory");
}
__device__ __forceinline__ void cp_wait1(){
    asm volatile("cp.async.wait_group 1;" ::: "memory");
}
__device__ __forceinline__ void pbar(int id){
    asm volatile("bar.sync %0, 64;" :: "r"(id) : "memory");
}

// ---------------- 1: node init + degree counts + inter weight + pool zero + cnt reset ----------------
__global__ void k_init(const float* __restrict__ x, const float* __restrict__ W,
                       const float* __restrict__ b,
                       const int* __restrict__ ei, const int* __restrict__ ee,
                       const float* __restrict__ pos){
    int blk = blockIdx.x;
    if (blk == 0 && threadIdx.x == 0){ g_cnt1 = 0; g_cnt2 = 0; }
    if (blk < NB_NODE){
        __shared__ float Ws[35*HH];
        __shared__ float xs[32*35];
        int t = threadIdx.x;           // 256
        int n0 = blk*32;
        for (int i = t; i < 35*HH; i += 256) Ws[i] = W[i];
        for (int i = t; i < 32*35; i += 256){
            int node = i/35, k = i - node*35;
            xs[i] = x[(n0+node)*35 + k];
        }
        __syncthreads();
        int c = t & 127;
        int g = t >> 7;
        float bb = b[c];
        for (int idx = 0; idx < 16; idx++){
            int node = g*16 + idx;
            float acc = bb;
            #pragma unroll
            for (int k = 0; k < 35; k++) acc += xs[node*35+k]*Ws[k*HH+c];
            g_h[(n0+node)*HH + c] = silu_f(acc);
        }
    } else {
        int t = (blk - NB_NODE)*256 + threadIdx.x;
        if (t < EI){
            atomicAdd(&g_degi[ei[EI+t]], 1);
        } else if (t < EI+EE){
            int e = t - EI;
            int s = ee[e], d = ee[EE+e];
            float dx = pos[s*3+0]-pos[d*3+0];
            float dy = pos[s*3+1]-pos[d*3+1];
            float dz = pos[s*3+2]-pos[d*3+2];
            g_wint[e] = __expf(-(dx*dx+dy*dy+dz*dz));
            atomicAdd(&g_dege[d], 1);
        } else if (t < EI+EE+GG*HH){
            g_pool[t - EI - EE] = 0.f;
        }
    }
}

// ---------------- 2: scan + offsets/cursors/factors + CSR fill ----------------
__global__ void __launch_bounds__(PREP_T) k_prep(const int* __restrict__ ei,
                                                 const float* __restrict__ ea,
                                                 const int* __restrict__ ee){
    __shared__ int s[1024];
    __shared__ int spi[128], spe[128];
    int b = blockIdx.x, b0 = b*1024, t = threadIdx.x;

    for (int pass = 0; pass < 2; pass++){
        const int* deg = pass ? g_dege : g_degi;
        int* off  = pass ? g_offe : g_offi;
        int* part = pass ? g_parte : g_parti;
        for (int i = t; i < 1024; i += 256){
            int n = b0 + i; s[i] = (n < NN) ? deg[n] : 0;
        }
        __syncthreads();
        for (int d = 1; d < 1024; d <<= 1){
            int tmp[4];
            #pragma unroll
            for (int j = 0; j < 4; j++){
                int i = t + j*256;
                tmp[j] = (i >= d) ? s[i-d] : 0;
            }
            __syncthreads();
            #pragma unroll
            for (int j = 0; j < 4; j++) s[t + j*256] += tmp[j];
            __syncthreads();
        }
        for (int i = t; i < 1024; i += 256){
            int n = b0 + i; if (n < NN) off[n+1] = s[i];
        }
        if (t == 0) atomicExch(&part[b], s[1023]);
        __syncthreads();
    }
    __threadfence();
    if (t == 0){
        atomicAdd(&g_cnt1, 1);
        int v; do { __nanosleep(128); v = atomicAdd(&g_cnt1, 0); } while (v < PREP_B);
    }
    __syncthreads();

    if (t < 128){
        spi[t] = (t < PREP_B) ? atomicAdd(&g_parti[t], 0) : 0;
        spe[t] = (t < PREP_B) ? atomicAdd(&g_parte[t], 0) : 0;
    }
    __syncthreads();
    for (int d = 1; d < 128; d <<= 1){
        int vi = 0, ve = 0;
        if (t < 128 && t >= d){ vi = spi[t-d]; ve = spe[t-d]; }
        __syncthreads();
        if (t < 128){ spi[t] += vi; spe[t] += ve; }
        __syncthreads();
    }
    int basei = (b > 0) ? spi[b-1] : 0;
    int basee = (b > 0) ? spe[b-1] : 0;

    for (int i = t; i < 1024; i += 256){
        int n = b0 + i;
        if (n >= NN) continue;
        int di = g_degi[n], de = g_dege[n];
        int oi = g_offi[n+1] + basei;
        int oe = g_offe[n+1] + basee;
        g_offi[n+1] = oi;
        g_offe[n+1] = oe;
        g_curi[n] = oi - di;
        g_cure[n] = oe - de;
        if (n == 0){ g_offi[0] = 0; g_offe[0] = 0; }
        float fdi = (float)di, fde = (float)de;
        float inv = 1.f/(fdi+1.f);
        g_sif[n] = inv;
        g_bfi[n] = fdi*inv;
        float L = logf(fde+1.f);
        g_sef[n] = L;
        g_bfe[n] = fde*L;
    }
    __threadfence();
    __syncthreads();
    if (t == 0){
        atomicAdd(&g_cnt2, 1);
        int v; do { __nanosleep(128); v = atomicAdd(&g_cnt2, 0); } while (v < PREP_B);
    }
    __syncthreads();

    for (int e = b*PREP_T + t; e < EI; e += PREP_NT){
        int s_ = ei[e], d = ei[EI+e];
        int p = atomicAdd(&g_curi[d], 1);
        g_srci[p] = s_; g_wi[p] = ea[e];
    }
    for (int e = b*PREP_T + t; e < EE; e += PREP_NT){
        int s_ = ee[e], d = ee[EE+e];
        int p = atomicAdd(&g_cure[d], 1);
        g_srce[p] = s_; g_we[p] = g_wint[e];
    }
}

// ---------------- per layer: transform v3 — pair-private strip pipelines ----------------
// 512 threads = 8 pairs; pair = 2 warps (intra warp + inter warp) over the same 8-row strip.
// Within a warp: thread = 8 rows x 4 cols of its matrix (round-14 proven inner GEMM).
__global__ void __launch_bounds__(512,1) k_transform(const float* __restrict__ Wi_,
                                                     const float* __restrict__ We_){
    extern __shared__ float sm[];
    float* ws = sm;                         // [128][256]: cols 0..127 Wi, 128..255 We
    int tid = threadIdx.x;
    int pair = tid >> 6;                    // 0..7
    int t64  = tid & 63;
    int mat  = (tid >> 5) & 1;              // warp parity within pair
    int lane = tid & 31;
    int c4 = lane*4;                        // cols 0..127 of own matrix
    int wcol = mat*128 + c4;                // column in combined ws
    float* dst = mat ? g_Ae : g_Ai;
    unsigned smbase = (unsigned)__cvta_generic_to_shared(sm);
    int barid = pair + 1;

    int u = blockIdx.x*8 + pair;            // pair-unit id 0..1183

    // prologue: issue first strip into buf0 (pair-cooperative)
    {
        int base = u*8;
        for (int i = t64; i < 264; i += 64){
            int row = i/33, sg = (i - row*33)*4;
            cp16(smbase + (PB(pair,0) + row*132 + sg)*4u, &g_h[(base+row)*HH + sg]);
        }
    }
    cp_commit();

    // load both W matrices (all 512 threads)
    for (int i = tid; i < 8192; i += 512){
        int k = i >> 6;
        int c = (i & 63)*4;
        float4 v = (c < 128) ? *(const float4*)&Wi_[k*128 + c]
                             : *(const float4*)&We_[k*128 + (c-128)];
        *(float4*)&ws[k*256 + c] = v;
    }
    __syncthreads();                        // W visible to all; only block barrier

    int buf = 0;
    for (int s = u; s < NSTRIP; s += NPAIRU, buf ^= 1){
        int n0 = s*8;
        int nxt = s + NPAIRU;
        if (nxt < NSTRIP){
            int base = nxt*8;
            unsigned boff = (unsigned)PB(pair, buf^1);
            for (int i = t64; i < 264; i += 64){
                int row = i/33, sg = (i - row*33)*4;
                cp16(smbase + (boff + row*132 + sg)*4u, &g_h[(base+row)*HH + sg]);
            }
        }
        cp_commit();
        cp_wait1();
        pbar(barid);                        // current strip visible to whole pair

        const float* ab = sm + PB(pair, buf);

        unsigned long long acc[8][2];
        #pragma unroll
        for (int r = 0; r < 8; r++){ acc[r][0] = 0ull; acc[r][1] = 0ull; }

        #pragma unroll 1
        for (int k0 = 0; k0 < 128; k0 += 4){
            float4 a4[8];
            #pragma unroll
            for (int r = 0; r < 8; r++) a4[r] = *(const float4*)&ab[r*132 + k0];  // warp-broadcast
            #pragma unroll
            for (int kk = 0; kk < 4; kk++){
                ulonglong2 w2 = *(const ulonglong2*)&ws[(k0+kk)*256 + wcol];
                #pragma unroll
                for (int r = 0; r < 8; r++){
                    float a = (kk==0)?a4[r].x:(kk==1)?a4[r].y:(kk==2)?a4[r].z:a4[r].w;
                    unsigned long long aa = dup2(a);
                    ffma2(acc[r][0], aa, w2.x);
                    ffma2(acc[r][1], aa, w2.y);
                }
            }
        }

        #pragma unroll
        for (int r = 0; r < 8; r++){
            float2 p0 = *(float2*)&acc[r][0];
            float2 p1 = *(float2*)&acc[r][1];
            *(float4*)&dst[(n0+r)*HH + c4] = make_float4(p0.x, p0.y, p1.x, p1.y);
        }
        pbar(barid);                        // pair done reading buf before it is refilled
    }
}

// ---------------- per layer: gather from Hp/Hl + epilogue + state + h update (+pool fuse) ----------------
__global__ void __launch_bounds__(256,5) k_gather2(const float* __restrict__ bi,
                                                   const float* __restrict__ be,
                                                   const int* __restrict__ batch,
                                                   int firstL, int lastL){
    int gw = (blockIdx.x*256 + threadIdx.x) >> 5;
    if (gw >= NN) return;
    int lane = threadIdx.x & 31;
    int c4 = lane*4;

    float sif = g_sif[gw], bfi = g_bfi[gw], sef = g_sef[gw], bfe = g_bfe[gw];
    float4 bi4 = *(const float4*)&bi[c4];
    float4 be4 = *(const float4*)&be[c4];
    float4 vo = make_float4(0,0,0,0), uo = make_float4(0,0,0,0);
    if (!firstL){
        vo = *(const float4*)&g_vp[gw*HH + c4];
        uo = *(const float4*)&g_vl[gw*HH + c4];
    }
    float4 hv = *(const float4*)&g_h[gw*HH + c4];

    float4 si;
    {
        int a0 = g_offi[gw], a1 = g_offi[gw+1];
        float4 x0 = make_float4(0,0,0,0), x1 = x0, x2 = x0, x3 = x0;
        int j = a0;
        for (; j + 4 <= a1; j += 4){
            int s0 = __ldg(&g_srci[j+0]); float w0 = __ldg(&g_wi[j+0]);
            int s1 = __ldg(&g_srci[j+1]); float w1 = __ldg(&g_wi[j+1]);
            int s2 = __ldg(&g_srci[j+2]); float w2 = __ldg(&g_wi[j+2]);
            int s3 = __ldg(&g_srci[j+3]); float w3 = __ldg(&g_wi[j+3]);
            float4 h0 = *(const float4*)&g_Ai[s0*HH + c4];
            float4 h1 = *(const float4*)&g_Ai[s1*HH + c4];
            float4 h2 = *(const float4*)&g_Ai[s2*HH + c4];
            float4 h3 = *(const float4*)&g_Ai[s3*HH + c4];
            x0.x += w0*h0.x; x0.y += w0*h0.y; x0.z += w0*h0.z; x0.w += w0*h0.w;
            x1.x += w1*h1.x; x1.y += w1*h1.y; x1.z += w1*h1.z; x1.w += w1*h1.w;
            x2.x += w2*h2.x; x2.y += w2*h2.y; x2.z += w2*h2.z; x2.w += w2*h2.w;
            x3.x += w3*h3.x; x3.y += w3*h3.y; x3.z += w3*h3.z; x3.w += w3*h3.w;
        }
        for (; j < a1; j++){
            int s = __ldg(&g_srci[j]); float w = __ldg(&g_wi[j]);
            float4 h0 = *(const float4*)&g_Ai[s*HH + c4];
            x0.x += w*h0.x; x0.y += w*h0.y; x0.z += w*h0.z; x0.w += w*h0.w;
        }
        si = make_float4(x0.x+x1.x+x2.x+x3.x, x0.y+x1.y+x2.y+x3.y,
                         x0.z+x1.z+x2.z+x3.z, x0.w+x1.w+x2.w+x3.w);
    }
    float4 se;
    {
        int a0 = g_offe[gw], a1 = g_offe[gw+1];
        float4 x0 = make_float4(0,0,0,0), x1 = x0, x2 = x0, x3 = x0;
        int j = a0;
        for (; j + 4 <= a1; j += 4){
            int s0 = __ldg(&g_srce[j+0]); float w0 = __ldg(&g_we[j+0]);
            int s1 = __ldg(&g_srce[j+1]); float w1 = __ldg(&g_we[j+1]);
            int s2 = __ldg(&g_srce[j+2]); float w2 = __ldg(&g_we[j+2]);
            int s3 = __ldg(&g_srce[j+3]); float w3 = __ldg(&g_we[j+3]);
            float4 h0 = *(const float4*)&g_Ae[s0*HH + c4];
            float4 h1 = *(const float4*)&g_Ae[s1*HH + c4];
            float4 h2 = *(const float4*)&g_Ae[s2*HH + c4];
            float4 h3 = *(const float4*)&g_Ae[s3*HH + c4];
            x0.x += w0*h0.x; x0.y += w0*h0.y; x0.z += w0*h0.z; x0.w += w0*h0.w;
            x1.x += w1*h1.x; x1.y += w1*h1.y; x1.z += w1*h1.z; x1.w += w1*h1.w;
            x2.x += w2*h2.x; x2.y += w2*h2.y; x2.z += w2*h2.z; x2.w += w2*h2.w;
            x3.x += w3*h3.x; x3.y += w3*h3.y; x3.z += w3*h3.z; x3.w += w3*h3.w;
        }
        for (; j < a1; j++){
            int s = __ldg(&g_srce[j]); float w = __ldg(&g_we[j]);
            float4 h0 = *(const float4*)&g_Ae[s*HH + c4];
            x0.x += w*h0.x; x0.y += w*h0.y; x0.z += w*h0.z; x0.w += w*h0.w;
        }
        se = make_float4(x0.x+x1.x+x2.x+x3.x, x0.y+x1.y+x2.y+x3.y,
                         x0.z+x1.z+x2.z+x3.z, x0.w+x1.w+x2.w+x3.w);
    }

    float4 v;
    v.x = silu_f(si.x*sif + bi4.x*bfi + vo.x);
    v.y = silu_f(si.y*sif + bi4.y*bfi + vo.y);
    v.z = silu_f(si.z*sif + bi4.z*bfi + vo.z);
    v.w = silu_f(si.w*sif + bi4.w*bfi + vo.w);
    float4 u;
    u.x = silu_f(se.x*sef + be4.x*bfe + uo.x);
    u.y = silu_f(se.y*sef + be4.y*bfe + uo.y);
    u.z = silu_f(se.z*sef + be4.z*bfe + uo.z);
    u.w = silu_f(se.w*sef + be4.w*bfe + uo.w);

    hv.x += v.x + u.x; hv.y += v.y + u.y; hv.z += v.z + u.z; hv.w += v.w + u.w;

    if (!lastL){
        *(float4*)&g_vp[gw*HH + c4] = v;
        *(float4*)&g_vl[gw*HH + c4] = u;
        *(float4*)&g_h[gw*HH + c4] = hv;
    } else {
        int bg = batch[gw];
        atomicAdd((float4*)&g_pool[bg*HH + c4], hv);
    }
}

// ---------------- FC head (+ degree re-zero) ----------------
__global__ void k_fc(const float* __restrict__ fcW, const float* __restrict__ fcb,
                     const float* __restrict__ gam, const float* __restrict__ bet,
                     const float* __restrict__ oW,  const float* __restrict__ ob,
                     float* __restrict__ out){
    int g = blockIdx.x, c = threadIdx.x;
    __shared__ float s[HH];
    __shared__ float red[HH];
    s[c] = g_pool[g*HH + c];
    for (int i = g*128 + c; i < NN; i += GG*128){ g_degi[i] = 0; g_dege[i] = 0; }
    __syncthreads();
    const float bns = rsqrtf(1.f + 1e-5f);
    for (int j = 0; j < 3; j++){
        const float* W = fcW + j*HH*HH;
        float acc = fcb[j*HH+c];
        #pragma unroll 8
        for (int k = 0; k < HH; k++) acc += s[k]*W[k*HH+c];
        acc = acc > 0.f ? acc : 0.01f*acc;
        acc = acc*bns*gam[j*HH+c] + bet[j*HH+c];
        __syncthreads();
        s[c] = acc;
        __syncthreads();
    }
    red[c] = s[c]*oW[c];
    __syncthreads();
    for (int o = 64; o > 0; o >>= 1){
        if (c < o) red[c] += red[c+o];
        __syncthreads();
    }
    if (c == 0) out[g] = red[0] + ob[0];
}

// ---------------- host ----------------
extern "C" void kernel_launch(void* const* d_in, const int* in_sizes, int n_in,
                              void* d_out, int out_size){
    const float* x    = (const float*)d_in[0];
    const int*   ei   = (const int*)  d_in[1];
    const int*   ee   = (const int*)  d_in[2];
    const float* pos  = (const float*)d_in[3];
    const float* ea   = (const float*)d_in[4];
    const int*   batch= (const int*)  d_in[5];
    const float* lnW  = (const float*)d_in[6];
    const float* lnb  = (const float*)d_in[7];
    const float* Wi   = (const float*)d_in[8];
    const float* bi   = (const float*)d_in[9];
    const float* We   = (const float*)d_in[10];
    const float* be   = (const float*)d_in[11];
    const float* fcW  = (const float*)d_in[12];
    const float* fcb  = (const float*)d_in[13];
    const float* gam  = (const float*)d_in[14];
    const float* bet  = (const float*)d_in[15];
    const float* oW   = (const float*)d_in[16];
    const float* ob   = (const float*)d_in[17];
    float* out = (float*)d_out;

    cudaFuncSetAttribute(k_transform, cudaFuncAttributeMaxDynamicSharedMemorySize, (int)SMEM_TRANS);

    k_init<<<NB_NODE + NB_CNT, 256>>>(x, lnW, lnb, ei, ee, pos);  // launch 1
    k_prep<<<PREP_B, PREP_T>>>(ei, ea, ee);                       // launch 2

    for (int l = 0; l < N_LAYERS; l++){
        k_transform<<<148, 512, SMEM_TRANS>>>(Wi + l*HH*HH, We + l*HH*HH); // launch 3,5,7,9
        k_gather2<<<(NN*32+255)/256, 256>>>(bi + l*HH, be + l*HH, batch,
                                            l == 0, l == N_LAYERS-1);      // launch 4 (ncu capture),6,8,10
    }

    k_fc<<<GG, 128>>>(fcW, fcb, gam, bet, oW, ob, out);           // launch 11
}

// round 17
// speedup vs baseline: 1.3392x; 1.0268x over previous
#include <cuda_runtime.h>
#include <cstdint>

#define NN 100000
#define NP 100032
#define EI 800000
#define EE 400000
#define HH 128
#define GG 256
#define N_LAYERS 4
#define NB_NODE 3125       // 3125*32 = 100000
#define NB_CNT  4816       // covers EI+EE+GG*HH threads
#define PREP_B 98
#define PREP_T 256
#define PREP_NT (PREP_B*PREP_T)

// transform v3: pair-private 8-row strips, no block barriers in loop
#define NSTRIP 12504       // NP/8
#define NPAIRU 1184        // 148 CTAs * 8 pairs
#define W_FLOATS 32768     // 128*256
#define PB(p,b) (W_FLOATS + (p)*2112 + (b)*1056)   // floats
#define SMEM_TRANS ((W_FLOATS + 8*2112)*sizeof(float))   // 198656 B

// ---------------- scratch ----------------
__device__ float g_h [NP*HH];
__device__ float g_vp[NP*HH];
__device__ float g_vl[NP*HH];
__device__ float g_Ai[NP*HH];   // Hp = h @ W_i
__device__ float g_Ae[NP*HH];   // Hl = h @ W_e
__device__ float g_wint[EE];
__device__ int   g_degi[NN];
__device__ int   g_dege[NN];
__device__ float g_sif[NP];
__device__ float g_bfi[NP];
__device__ float g_sef[NP];
__device__ float g_bfe[NP];
__device__ int   g_offi[NN+1];
__device__ int   g_offe[NN+1];
__device__ int   g_curi[NN];
__device__ int   g_cure[NN];
__device__ int   g_srci[EI];
__device__ float g_wi[EI];
__device__ int   g_srce[EE];
__device__ float g_we[EE];
__device__ int   g_parti[128];
__device__ int   g_parte[128];
__device__ int   g_cnt1;
__device__ int   g_cnt2;
__device__ float g_pool[GG*HH];

__device__ __forceinline__ float silu_f(float x){ return x / (1.f + __expf(-x)); }
__device__ __forceinline__ unsigned long long dup2(float a){
    unsigned long long r; asm("mov.b64 %0, {%1, %1};" : "=l"(r) : "f"(a)); return r;
}
__device__ __forceinline__ void ffma2(unsigned long long& acc, unsigned long long a, unsigned long long b){
    asm("fma.rn.f32x2 %0, %1, %2, %0;" : "+l"(acc) : "l"(a), "l"(b));
}
__device__ __forceinline__ void cp16(unsigned dst, const void* src){
    asm volatile("cp.async.cg.shared.global [%0], [%1], 16;" :: "r"(dst), "l"(src));
}
__device__ __forceinline__ void cp_commit(){
    asm volatile("cp.async.commit_group;" ::: "memory");
}
__device__ __forceinline__ void cp_wait1(){
    asm volatile("cp.async.wait_group 1;" ::: "memory");
}
__device__ __forceinline__ void pbar(int id){
    asm volatile("bar.sync %0, 64;" :: "r"(id) : "memory");
}
// streaming (evict-first) float4 load/store
__device__ __forceinline__ float4 ld_cs4(const float* p){
    float4 v;
    asm volatile("ld.global.cs.v4.f32 {%0,%1,%2,%3}, [%4];"
        : "=f"(v.x), "=f"(v.y), "=f"(v.z), "=f"(v.w) : "l"(p));
    return v;
}
__device__ __forceinline__ void st_cs4(float* p, float4 v){
    asm volatile("st.global.cs.v4.f32 [%0], {%1,%2,%3,%4};"
        :: "l"(p), "f"(v.x), "f"(v.y), "f"(v.z), "f"(v.w) : "memory");
}

// ---------------- 1: node init + degree counts + inter weight + pool zero + cnt reset ----------------
__global__ void k_init(const float* __restrict__ x, const float* __restrict__ W,
                       const float* __restrict__ b,
                       const int* __restrict__ ei, const int* __restrict__ ee,
                       const float* __restrict__ pos){
    int blk = blockIdx.x;
    if (blk == 0 && threadIdx.x == 0){ g_cnt1 = 0; g_cnt2 = 0; }
    if (blk < NB_NODE){
        __shared__ float Ws[35*HH];
        __shared__ float xs[32*35];
        int t = threadIdx.x;           // 256
        int n0 = blk*32;
        for (int i = t; i < 35*HH; i += 256) Ws[i] = W[i];
        for (int i = t; i < 32*35; i += 256){
            int node = i/35, k = i - node*35;
            xs[i] = x[(n0+node)*35 + k];
        }
        __syncthreads();
        int c = t & 127;
        int g = t >> 7;
        float bb = b[c];
        for (int idx = 0; idx < 16; idx++){
            int node = g*16 + idx;
            float acc = bb;
            #pragma unroll
            for (int k = 0; k < 35; k++) acc += xs[node*35+k]*Ws[k*HH+c];
            g_h[(n0+node)*HH + c] = silu_f(acc);
        }
    } else {
        int t = (blk - NB_NODE)*256 + threadIdx.x;
        if (t < EI){
            atomicAdd(&g_degi[ei[EI+t]], 1);
        } else if (t < EI+EE){
            int e = t - EI;
            int s = ee[e], d = ee[EE+e];
            float dx = pos[s*3+0]-pos[d*3+0];
            float dy = pos[s*3+1]-pos[d*3+1];
            float dz = pos[s*3+2]-pos[d*3+2];
            g_wint[e] = __expf(-(dx*dx+dy*dy+dz*dz));
            atomicAdd(&g_dege[d], 1);
        } else if (t < EI+EE+GG*HH){
            g_pool[t - EI - EE] = 0.f;
        }
    }
}

// ---------------- 2: scan + offsets/cursors/factors + CSR fill ----------------
__global__ void __launch_bounds__(PREP_T) k_prep(const int* __restrict__ ei,
                                                 const float* __restrict__ ea,
                                                 const int* __restrict__ ee){
    __shared__ int s[1024];
    __shared__ int spi[128], spe[128];
    int b = blockIdx.x, b0 = b*1024, t = threadIdx.x;

    for (int pass = 0; pass < 2; pass++){
        const int* deg = pass ? g_dege : g_degi;
        int* off  = pass ? g_offe : g_offi;
        int* part = pass ? g_parte : g_parti;
        for (int i = t; i < 1024; i += 256){
            int n = b0 + i; s[i] = (n < NN) ? deg[n] : 0;
        }
        __syncthreads();
        for (int d = 1; d < 1024; d <<= 1){
            int tmp[4];
            #pragma unroll
            for (int j = 0; j < 4; j++){
                int i = t + j*256;
                tmp[j] = (i >= d) ? s[i-d] : 0;
            }
            __syncthreads();
            #pragma unroll
            for (int j = 0; j < 4; j++) s[t + j*256] += tmp[j];
            __syncthreads();
        }
        for (int i = t; i < 1024; i += 256){
            int n = b0 + i; if (n < NN) off[n+1] = s[i];
        }
        if (t == 0) atomicExch(&part[b], s[1023]);
        __syncthreads();
    }
    __threadfence();
    if (t == 0){
        atomicAdd(&g_cnt1, 1);
        int v; do { __nanosleep(128); v = atomicAdd(&g_cnt1, 0); } while (v < PREP_B);
    }
    __syncthreads();

    if (t < 128){
        spi[t] = (t < PREP_B) ? atomicAdd(&g_parti[t], 0) : 0;
        spe[t] = (t < PREP_B) ? atomicAdd(&g_parte[t], 0) : 0;
    }
    __syncthreads();
    for (int d = 1; d < 128; d <<= 1){
        int vi = 0, ve = 0;
        if (t < 128 && t >= d){ vi = spi[t-d]; ve = spe[t-d]; }
        __syncthreads();
        if (t < 128){ spi[t] += vi; spe[t] += ve; }
        __syncthreads();
    }
    int basei = (b > 0) ? spi[b-1] : 0;
    int basee = (b > 0) ? spe[b-1] : 0;

    for (int i = t; i < 1024; i += 256){
        int n = b0 + i;
        if (n >= NN) continue;
        int di = g_degi[n], de = g_dege[n];
        int oi = g_offi[n+1] + basei;
        int oe = g_offe[n+1] + basee;
        g_offi[n+1] = oi;
        g_offe[n+1] = oe;
        g_curi[n] = oi - di;
        g_cure[n] = oe - de;
        if (n == 0){ g_offi[0] = 0; g_offe[0] = 0; }
        float fdi = (float)di, fde = (float)de;
        float inv = 1.f/(fdi+1.f);
        g_sif[n] = inv;
        g_bfi[n] = fdi*inv;
        float L = logf(fde+1.f);
        g_sef[n] = L;
        g_bfe[n] = fde*L;
    }
    __threadfence();
    __syncthreads();
    if (t == 0){
        atomicAdd(&g_cnt2, 1);
        int v; do { __nanosleep(128); v = atomicAdd(&g_cnt2, 0); } while (v < PREP_B);
    }
    __syncthreads();

    for (int e = b*PREP_T + t; e < EI; e += PREP_NT){
        int s_ = ei[e], d = ei[EI+e];
        int p = atomicAdd(&g_curi[d], 1);
        g_srci[p] = s_; g_wi[p] = ea[e];
    }
    for (int e = b*PREP_T + t; e < EE; e += PREP_NT){
        int s_ = ee[e], d = ee[EE+e];
        int p = atomicAdd(&g_cure[d], 1);
        g_srce[p] = s_; g_we[p] = g_wint[e];
    }
}

// ---------------- per layer: transform v3 — pair-private strip pipelines ----------------
__global__ void __launch_bounds__(512,1) k_transform(const float* __restrict__ Wi_,
                                                     const float* __restrict__ We_){
    extern __shared__ float sm[];
    float* ws = sm;                         // [128][256]: cols 0..127 Wi, 128..255 We
    int tid = threadIdx.x;
    int pair = tid >> 6;                    // 0..7
    int t64  = tid & 63;
    int mat  = (tid >> 5) & 1;              // warp parity within pair
    int lane = tid & 31;
    int c4 = lane*4;                        // cols 0..127 of own matrix
    int wcol = mat*128 + c4;                // column in combined ws
    float* dst = mat ? g_Ae : g_Ai;
    unsigned smbase = (unsigned)__cvta_generic_to_shared(sm);
    int barid = pair + 1;

    int u = blockIdx.x*8 + pair;            // pair-unit id 0..1183

    // prologue: issue first strip into buf0 (pair-cooperative)
    {
        int base = u*8;
        for (int i = t64; i < 264; i += 64){
            int row = i/33, sg = (i - row*33)*4;
            cp16(smbase + (PB(pair,0) + row*132 + sg)*4u, &g_h[(base+row)*HH + sg]);
        }
    }
    cp_commit();

    // load both W matrices (all 512 threads)
    for (int i = tid; i < 8192; i += 512){
        int k = i >> 6;
        int c = (i & 63)*4;
        float4 v = (c < 128) ? *(const float4*)&Wi_[k*128 + c]
                             : *(const float4*)&We_[k*128 + (c-128)];
        *(float4*)&ws[k*256 + c] = v;
    }
    __syncthreads();                        // W visible to all; only block barrier

    int buf = 0;
    for (int s = u; s < NSTRIP; s += NPAIRU, buf ^= 1){
        int n0 = s*8;
        int nxt = s + NPAIRU;
        if (nxt < NSTRIP){
            int base = nxt*8;
            unsigned boff = (unsigned)PB(pair, buf^1);
            for (int i = t64; i < 264; i += 64){
                int row = i/33, sg = (i - row*33)*4;
                cp16(smbase + (boff + row*132 + sg)*4u, &g_h[(base+row)*HH + sg]);
            }
        }
        cp_commit();
        cp_wait1();
        pbar(barid);                        // current strip visible to whole pair

        const float* ab = sm + PB(pair, buf);

        unsigned long long acc[8][2];
        #pragma unroll
        for (int r = 0; r < 8; r++){ acc[r][0] = 0ull; acc[r][1] = 0ull; }

        #pragma unroll 1
        for (int k0 = 0; k0 < 128; k0 += 4){
            float4 a4[8];
            #pragma unroll
            for (int r = 0; r < 8; r++) a4[r] = *(const float4*)&ab[r*132 + k0];  // warp-broadcast
            #pragma unroll
            for (int kk = 0; kk < 4; kk++){
                ulonglong2 w2 = *(const ulonglong2*)&ws[(k0+kk)*256 + wcol];
                #pragma unroll
                for (int r = 0; r < 8; r++){
                    float a = (kk==0)?a4[r].x:(kk==1)?a4[r].y:(kk==2)?a4[r].z:a4[r].w;
                    unsigned long long aa = dup2(a);
                    ffma2(acc[r][0], aa, w2.x);
                    ffma2(acc[r][1], aa, w2.y);
                }
            }
        }

        #pragma unroll
        for (int r = 0; r < 8; r++){
            float2 p0 = *(float2*)&acc[r][0];
            float2 p1 = *(float2*)&acc[r][1];
            *(float4*)&dst[(n0+r)*HH + c4] = make_float4(p0.x, p0.y, p1.x, p1.y);
        }
        pbar(barid);                        // pair done reading buf before it is refilled
    }
}

// ---------------- per layer: gather from Hp/Hl + epilogue + state + h update (+pool fuse) ----------------
// State streams (vp/vl/h) use evict-first (.cs) so Hp/Hl stay L2-resident for the random gathers.
__global__ void __launch_bounds__(256,5) k_gather2(const float* __restrict__ bi,
                                                   const float* __restrict__ be,
                                                   const int* __restrict__ batch,
                                                   int firstL, int lastL){
    int gw = (blockIdx.x*256 + threadIdx.x) >> 5;
    if (gw >= NN) return;
    int lane = threadIdx.x & 31;
    int c4 = lane*4;

    float sif = g_sif[gw], bfi = g_bfi[gw], sef = g_sef[gw], bfe = g_bfe[gw];
    float4 bi4 = *(const float4*)&bi[c4];
    float4 be4 = *(const float4*)&be[c4];
    float4 vo = make_float4(0,0,0,0), uo = make_float4(0,0,0,0);
    if (!firstL){
        vo = ld_cs4(&g_vp[gw*HH + c4]);
        uo = ld_cs4(&g_vl[gw*HH + c4]);
    }
    float4 hv = ld_cs4(&g_h[gw*HH + c4]);

    float4 si;
    {
        int a0 = g_offi[gw], a1 = g_offi[gw+1];
        float4 x0 = make_float4(0,0,0,0), x1 = x0, x2 = x0, x3 = x0;
        int j = a0;
        for (; j + 4 <= a1; j += 4){
            int s0 = __ldg(&g_srci[j+0]); float w0 = __ldg(&g_wi[j+0]);
            int s1 = __ldg(&g_srci[j+1]); float w1 = __ldg(&g_wi[j+1]);
            int s2 = __ldg(&g_srci[j+2]); float w2 = __ldg(&g_wi[j+2]);
            int s3 = __ldg(&g_srci[j+3]); float w3 = __ldg(&g_wi[j+3]);
            float4 h0 = *(const float4*)&g_Ai[s0*HH + c4];
            float4 h1 = *(const float4*)&g_Ai[s1*HH + c4];
            float4 h2 = *(const float4*)&g_Ai[s2*HH + c4];
            float4 h3 = *(const float4*)&g_Ai[s3*HH + c4];
            x0.x += w0*h0.x; x0.y += w0*h0.y; x0.z += w0*h0.z; x0.w += w0*h0.w;
            x1.x += w1*h1.x; x1.y += w1*h1.y; x1.z += w1*h1.z; x1.w += w1*h1.w;
            x2.x += w2*h2.x; x2.y += w2*h2.y; x2.z += w2*h2.z; x2.w += w2*h2.w;
            x3.x += w3*h3.x; x3.y += w3*h3.y; x3.z += w3*h3.z; x3.w += w3*h3.w;
        }
        for (; j < a1; j++){
            int s = __ldg(&g_srci[j]); float w = __ldg(&g_wi[j]);
            float4 h0 = *(const float4*)&g_Ai[s*HH + c4];
            x0.x += w*h0.x; x0.y += w*h0.y; x0.z += w*h0.z; x0.w += w*h0.w;
        }
        si = make_float4(x0.x+x1.x+x2.x+x3.x, x0.y+x1.y+x2.y+x3.y,
                         x0.z+x1.z+x2.z+x3.z, x0.w+x1.w+x2.w+x3.w);
    }
    float4 se;
    {
        int a0 = g_offe[gw], a1 = g_offe[gw+1];
        float4 x0 = make_float4(0,0,0,0), x1 = x0, x2 = x0, x3 = x0;
        int j = a0;
        for (; j + 4 <= a1; j += 4){
            int s0 = __ldg(&g_srce[j+0]); float w0 = __ldg(&g_we[j+0]);
            int s1 = __ldg(&g_srce[j+1]); float w1 = __ldg(&g_we[j+1]);
            int s2 = __ldg(&g_srce[j+2]); float w2 = __ldg(&g_we[j+2]);
            int s3 = __ldg(&g_srce[j+3]); float w3 = __ldg(&g_we[j+3]);
            float4 h0 = *(const float4*)&g_Ae[s0*HH + c4];
            float4 h1 = *(const float4*)&g_Ae[s1*HH + c4];
            float4 h2 = *(const float4*)&g_Ae[s2*HH + c4];
            float4 h3 = *(const float4*)&g_Ae[s3*HH + c4];
            x0.x += w0*h0.x; x0.y += w0*h0.y; x0.z += w0*h0.z; x0.w += w0*h0.w;
            x1.x += w1*h1.x; x1.y += w1*h1.y; x1.z += w1*h1.z; x1.w += w1*h1.w;
            x2.x += w2*h2.x; x2.y += w2*h2.y; x2.z += w2*h2.z; x2.w += w2*h2.w;
            x3.x += w3*h3.x; x3.y += w3*h3.y; x3.z += w3*h3.z; x3.w += w3*h3.w;
        }
        for (; j < a1; j++){
            int s = __ldg(&g_srce[j]); float w = __ldg(&g_we[j]);
            float4 h0 = *(const float4*)&g_Ae[s*HH + c4];
            x0.x += w*h0.x; x0.y += w*h0.y; x0.z += w*h0.z; x0.w += w*h0.w;
        }
        se = make_float4(x0.x+x1.x+x2.x+x3.x, x0.y+x1.y+x2.y+x3.y,
                         x0.z+x1.z+x2.z+x3.z, x0.w+x1.w+x2.w+x3.w);
    }

    float4 v;
    v.x = silu_f(si.x*sif + bi4.x*bfi + vo.x);
    v.y = silu_f(si.y*sif + bi4.y*bfi + vo.y);
    v.z = silu_f(si.z*sif + bi4.z*bfi + vo.z);
    v.w = silu_f(si.w*sif + bi4.w*bfi + vo.w);
    float4 u;
    u.x = silu_f(se.x*sef + be4.x*bfe + uo.x);
    u.y = silu_f(se.y*sef + be4.y*bfe + uo.y);
    u.z = silu_f(se.z*sef + be4.z*bfe + uo.z);
    u.w = silu_f(se.w*sef + be4.w*bfe + uo.w);

    hv.x += v.x + u.x; hv.y += v.y + u.y; hv.z += v.z + u.z; hv.w += v.w + u.w;

    if (!lastL){
        st_cs4(&g_vp[gw*HH + c4], v);
        st_cs4(&g_vl[gw*HH + c4], u);
        st_cs4(&g_h[gw*HH + c4], hv);
    } else {
        int bg = batch[gw];
        atomicAdd((float4*)&g_pool[bg*HH + c4], hv);
    }
}

// ---------------- FC head (+ degree re-zero) ----------------
__global__ void k_fc(const float* __restrict__ fcW, const float* __restrict__ fcb,
                     const float* __restrict__ gam, const float* __restrict__ bet,
                     const float* __restrict__ oW,  const float* __restrict__ ob,
                     float* __restrict__ out){
    int g = blockIdx.x, c = threadIdx.x;
    __shared__ float s[HH];
    __shared__ float red[HH];
    s[c] = g_pool[g*HH + c];
    for (int i = g*128 + c; i < NN; i += GG*128){ g_degi[i] = 0; g_dege[i] = 0; }
    __syncthreads();
    const float bns = rsqrtf(1.f + 1e-5f);
    for (int j = 0; j < 3; j++){
        const float* W = fcW + j*HH*HH;
        float acc = fcb[j*HH+c];
        #pragma unroll 8
        for (int k = 0; k < HH; k++) acc += s[k]*W[k*HH+c];
        acc = acc > 0.f ? acc : 0.01f*acc;
        acc = acc*bns*gam[j*HH+c] + bet[j*HH+c];
        __syncthreads();
        s[c] = acc;
        __syncthreads();
    }
    red[c] = s[c]*oW[c];
    __syncthreads();
    for (int o = 64; o > 0; o >>= 1){
        if (c < o) red[c] += red[c+o];
        __syncthreads();
    }
    if (c == 0) out[g] = red[0] + ob[0];
}

// ---------------- host ----------------
extern "C" void kernel_launch(void* const* d_in, const int* in_sizes, int n_in,
                              void* d_out, int out_size){
    const float* x    = (const float*)d_in[0];
    const int*   ei   = (const int*)  d_in[1];
    const int*   ee   = (const int*)  d_in[2];
    const float* pos  = (const float*)d_in[3];
    const float* ea   = (const float*)d_in[4];
    const int*   batch= (const int*)  d_in[5];
    const float* lnW  = (const float*)d_in[6];
    const float* lnb  = (const float*)d_in[7];
    const float* Wi   = (const float*)d_in[8];
    const float* bi   = (const float*)d_in[9];
    const float* We   = (const float*)d_in[10];
    const float* be   = (const float*)d_in[11];
    const float* fcW  = (const float*)d_in[12];
    const float* fcb  = (const float*)d_in[13];
    const float* gam  = (const float*)d_in[14];
    const float* bet  = (const float*)d_in[15];
    const float* oW   = (const float*)d_in[16];
    const float* ob   = (const float*)d_in[17];
    float* out = (float*)d_out;

    cudaFuncSetAttribute(k_transform, cudaFuncAttributeMaxDynamicSharedMemorySize, (int)SMEM_TRANS);

    k_init<<<NB_NODE + NB_CNT, 256>>>(x, lnW, lnb, ei, ee, pos);  // launch 1
    k_prep<<<PREP_B, PREP_T>>>(ei, ea, ee);                       // launch 2

    for (int l = 0; l < N_LAYERS; l++){
        k_transform<<<148, 512, SMEM_TRANS>>>(Wi + l*HH*HH, We + l*HH*HH); // launch 3,5,7,9
        k_gather2<<<(NN*32+255)/256, 256>>>(bi + l*HH, be + l*HH, batch,
                                            l == 0, l == N_LAYERS-1);      // launch 4 (ncu capture),6,8,10
    }

    k_fc<<<GG, 128>>>(fcW, fcb, gam, bet, oW, ob, out);           // launch 11
}